// round 8
// baseline (speedup 1.0000x reference)
#include <cuda_runtime.h>
#include <cstdint>

#define BATCH 16384
#define NEG 5
#define ROWS 7                                  // u, v, 5 negs
#define WARPS 4
#define THREADS (WARPS * 32)                    // 128
#define EPW 4                                   // elements per warp
#define EPB (WARPS * EPW)                       // 16 elements per block
#define NBLOCKS (BATCH / EPB)                   // 1024
#define ROW_BYTES 512
#define WARP_TX (EPW * ROWS * ROW_BYTES)        // 14336 bytes per warp
#define STAGE_BYTES (EPB * ROWS * ROW_BYTES)    // 57344
#define SMEM_DYN (STAGE_BYTES + 64)             // + mbarrier area

__device__ float g_partials[NBLOCKS];
__device__ unsigned int g_count;                // zero-init; last block resets

__device__ __forceinline__ float logsig(float x) {
    return fminf(x, 0.0f) - log1pf(expf(-fabsf(x)));
}

__device__ __forceinline__ void mbar_wait(uint32_t mbar, uint32_t parity) {
    uint32_t done;
    asm volatile(
        "{\n\t.reg .pred p;\n\t"
        "mbarrier.try_wait.parity.acquire.cta.shared::cta.b64 p, [%1], %2;\n\t"
        "selp.b32 %0, 1, 0, p;\n\t}"
        : "=r"(done) : "r"(mbar), "r"(parity) : "memory");
    if (!done) {
        asm volatile(
            "{\n\t.reg .pred P1;\n\t"
            "WAIT_LOOP_%=:\n\t"
            "mbarrier.try_wait.parity.acquire.cta.shared::cta.b64 P1, [%0], %1, 0x989680;\n\t"
            "@P1 bra.uni WAIT_DONE_%=;\n\t"
            "bra.uni WAIT_LOOP_%=;\n\t"
            "WAIT_DONE_%=:\n\t}"
            :: "r"(mbar), "r"(parity) : "memory");
    }
}

__global__ void __launch_bounds__(THREADS)
sg_fused(const float* __restrict__ emb,
         const int* __restrict__ centers,
         const int* __restrict__ contexts,
         const int* __restrict__ negs,
         float* __restrict__ out) {
    extern __shared__ __align__(16) char smem_raw[];
    float4* stage4 = reinterpret_cast<float4*>(smem_raw);   // [EPB][ROWS][32] float4
    const uint32_t smem_base = (uint32_t)__cvta_generic_to_shared(smem_raw);
    const uint32_t mbar_base = smem_base + STAGE_BYTES;     // 4 x 8B barriers

    __shared__ float smw[WARPS];
    __shared__ float red[THREADS];
    __shared__ bool is_last;

    const int lane = threadIdx.x & 31;
    const int warp = threadIdx.x >> 5;
    const uint32_t my_mbar = mbar_base + warp * 8;

    // Init per-warp mbarriers (arrive count = 1: the expect_tx arrival).
    if (threadIdx.x < WARPS) {
        uint32_t mb = mbar_base + threadIdx.x * 8;
        asm volatile("mbarrier.init.shared.b64 [%0], %1;" :: "r"(mb), "r"(1) : "memory");
    }
    __syncthreads();
    if (threadIdx.x == 0)
        asm volatile("fence.proxy.async.shared::cta;" ::: "memory");
    __syncthreads();

    // Lanes 0..27: one (element, row) pair each.
    const int t  = lane % 7;                       // row type within element
    const int el = warp * EPW + lane / 7;          // element within block (0..15)
    const int bb = blockIdx.x * EPB + el;          // global batch element

    int idx = 0;
    if (lane < 28) {
        if (t == 0)      idx = centers[bb];
        else if (t == 1) idx = contexts[bb];
        else             idx = negs[bb * NEG + (t - 2)];
    }

    // Post expected bytes, then issue 28 bulk copies (one per lane) onto the
    // TMA/bulk engine. No LSU dest registers, no L1tex MSHR pressure.
    if (lane == 0)
        asm volatile("mbarrier.arrive.expect_tx.shared.b64 _, [%0], %1;"
                     :: "r"(my_mbar), "r"((uint32_t)WARP_TX) : "memory");

    if (lane < 28) {
        uint32_t dst = smem_base + (uint32_t)(el * ROWS + t) * ROW_BYTES;
        const float* src = emb + (size_t)idx * 128;
        asm volatile(
            "cp.async.bulk.shared::cta.global.mbarrier::complete_tx::bytes "
            "[%0], [%1], %2, [%3];"
            :: "r"(dst), "l"(src), "r"((uint32_t)ROW_BYTES), "r"(my_mbar)
            : "memory");
    }

    // Wait for this warp's 14KB to land.
    mbar_wait(my_mbar, 0);

    // Compute 4 elements per warp.
    float acc = 0.0f;
    #pragma unroll
    for (int e = 0; e < EPW; e++) {
        const float4* st = stage4 + (size_t)(warp * EPW + e) * ROWS * 32;
        const float4 u  = st[0 * 32 + lane];
        const float4 v  = st[1 * 32 + lane];
        const float4 w0 = st[2 * 32 + lane];
        const float4 w1 = st[3 * 32 + lane];
        const float4 w2 = st[4 * 32 + lane];
        const float4 w3 = st[5 * 32 + lane];
        const float4 w4 = st[6 * 32 + lane];

        float4 ns;
        ns.x = w0.x + w1.x + w2.x + w3.x + w4.x;
        ns.y = w0.y + w1.y + w2.y + w3.y + w4.y;
        ns.z = w0.z + w1.z + w2.z + w3.z + w4.z;
        ns.w = w0.w + w1.w + w2.w + w3.w + w4.w;

        float pos = u.x * v.x  + u.y * v.y  + u.z * v.z  + u.w * v.w;
        float neg = u.x * ns.x + u.y * ns.y + u.z * ns.z + u.w * ns.w;

        #pragma unroll
        for (int o = 16; o > 0; o >>= 1) {
            pos += __shfl_xor_sync(0xffffffffu, pos, o);
            neg += __shfl_xor_sync(0xffffffffu, neg, o);
        }
        if (lane == 0)
            acc += logsig(pos) + logsig(-neg);
    }

    if (lane == 0) smw[warp] = acc;
    __syncthreads();

    if (threadIdx.x == 0) {
        float s = smw[0] + smw[1] + smw[2] + smw[3];
        g_partials[blockIdx.x] = s;
        __threadfence();
        unsigned int c = atomicAdd(&g_count, 1u);
        is_last = (c == NBLOCKS - 1);
    }
    __syncthreads();

    // Last block: deterministic fixed-order reduction of 1024 partials.
    if (is_last) {
        float s = 0.0f;
        #pragma unroll
        for (int i = 0; i < NBLOCKS / THREADS; i++)    // 8 per thread
            s += g_partials[threadIdx.x + i * THREADS];
        red[threadIdx.x] = s;
        __syncthreads();
        #pragma unroll
        for (int o = THREADS / 2; o > 0; o >>= 1) {
            if (threadIdx.x < o) red[threadIdx.x] += red[threadIdx.x + o];
            __syncthreads();
        }
        if (threadIdx.x == 0) {
            out[0] = -red[0];
            g_count = 0;    // reset for next graph replay (determinism)
        }
    }
}

extern "C" void kernel_launch(void* const* d_in, const int* in_sizes, int n_in,
                              void* d_out, int out_size) {
    const float* emb      = (const float*)d_in[0];
    const int*   centers  = (const int*)  d_in[1];
    const int*   contexts = (const int*)  d_in[2];
    const int*   negs     = (const int*)  d_in[3];
    float*       out      = (float*)d_out;

    static bool attr_set = false;
    if (!attr_set) {
        cudaFuncSetAttribute(sg_fused,
                             cudaFuncAttributeMaxDynamicSharedMemorySize,
                             SMEM_DYN);
        attr_set = true;
    }
    sg_fused<<<NBLOCKS, THREADS, SMEM_DYN>>>(emb, centers, contexts, negs, out);
}

// round 9
// speedup vs baseline: 1.3459x; 1.3459x over previous
#include <cuda_runtime.h>

#define BATCH 16384
#define NEG 5
#define WARPS_PER_BLOCK 8
#define THREADS (WARPS_PER_BLOCK * 32)          // 256
#define NBLOCKS (BATCH / WARPS_PER_BLOCK)       // 2048

__device__ float g_partials[NBLOCKS];
__device__ unsigned int g_count;                // zero-init; last block resets

__device__ __forceinline__ float logsig(float x) {
    // stable log(sigmoid(x)) = min(x,0) - log1p(exp(-|x|))
    return fminf(x, 0.0f) - log1pf(expf(-fabsf(x)));
}

__global__ void __launch_bounds__(THREADS, 8)
sg_fused(const float* __restrict__ emb,
         const int* __restrict__ centers,
         const int* __restrict__ contexts,
         const int* __restrict__ negs,
         float* __restrict__ out) {
    const int lane = threadIdx.x & 31;
    const int warp = threadIdx.x >> 5;
    const int b = blockIdx.x * WARPS_PER_BLOCK + warp;

    const float4* e4 = reinterpret_cast<const float4*>(emb);

    // Index loads (coalesced, tiny).
    const int ic = centers[b];
    const int it = contexts[b];
    const int in0 = negs[b * NEG + 0];
    const int in1 = negs[b * NEG + 1];
    const int in2 = negs[b * NEG + 2];
    const int in3 = negs[b * NEG + 3];
    const int in4 = negs[b * NEG + 4];

    // Row gathers: .cg -> bypass L1 allocation (zero reuse), straight from L2.
    // 7 independent LDG.128.CG issued back-to-back per warp.
    const float4 u  = __ldcg(e4 + (size_t)ic  * 32 + lane);
    const float4 v  = __ldcg(e4 + (size_t)it  * 32 + lane);
    const float4 w0 = __ldcg(e4 + (size_t)in0 * 32 + lane);
    const float4 w1 = __ldcg(e4 + (size_t)in1 * 32 + lane);
    const float4 w2 = __ldcg(e4 + (size_t)in2 * 32 + lane);
    const float4 w3 = __ldcg(e4 + (size_t)in3 * 32 + lane);
    const float4 w4 = __ldcg(e4 + (size_t)in4 * 32 + lane);

    // sum_k (u . nv_k) == u . (sum_k nv_k)
    float4 ns;
    ns.x = w0.x + w1.x + w2.x + w3.x + w4.x;
    ns.y = w0.y + w1.y + w2.y + w3.y + w4.y;
    ns.z = w0.z + w1.z + w2.z + w3.z + w4.z;
    ns.w = w0.w + w1.w + w2.w + w3.w + w4.w;

    float pos = u.x * v.x  + u.y * v.y  + u.z * v.z  + u.w * v.w;
    float neg = u.x * ns.x + u.y * ns.y + u.z * ns.z + u.w * ns.w;

    #pragma unroll
    for (int o = 16; o > 0; o >>= 1) {
        pos += __shfl_xor_sync(0xffffffffu, pos, o);
        neg += __shfl_xor_sync(0xffffffffu, neg, o);
    }

    __shared__ float sm[WARPS_PER_BLOCK];
    __shared__ bool is_last;
    if (lane == 0)
        sm[warp] = logsig(pos) + logsig(-neg);
    __syncthreads();

    if (threadIdx.x == 0) {
        float s = 0.0f;
        #pragma unroll
        for (int i = 0; i < WARPS_PER_BLOCK; i++) s += sm[i];
        g_partials[blockIdx.x] = s;
        __threadfence();
        unsigned int t = atomicAdd(&g_count, 1u);
        is_last = (t == NBLOCKS - 1);
    }
    __syncthreads();

    // Last block: deterministic fixed-order reduction of 2048 partials.
    if (is_last) {
        __shared__ float red[THREADS];
        float s = 0.0f;
        #pragma unroll
        for (int i = 0; i < NBLOCKS / THREADS; i++)     // 8 per thread
            s += g_partials[threadIdx.x + i * THREADS];
        red[threadIdx.x] = s;
        __syncthreads();
        #pragma unroll
        for (int o = THREADS / 2; o > 0; o >>= 1) {
            if (threadIdx.x < o) red[threadIdx.x] += red[threadIdx.x + o];
            __syncthreads();
        }
        if (threadIdx.x == 0) {
            out[0] = -red[0];
            g_count = 0;    // reset for next graph replay (determinism)
        }
    }
}

extern "C" void kernel_launch(void* const* d_in, const int* in_sizes, int n_in,
                              void* d_out, int out_size) {
    const float* emb      = (const float*)d_in[0];
    const int*   centers  = (const int*)  d_in[1];
    const int*   contexts = (const int*)  d_in[2];
    const int*   negs     = (const int*)  d_in[3];
    float*       out      = (float*)d_out;

    sg_fused<<<NBLOCKS, THREADS>>>(emb, centers, contexts, negs, out);
}